// round 16
// baseline (speedup 1.0000x reference)
#include <cuda_runtime.h>
#include <cuda_fp16.h>
#include <cstdint>

// ============================================================================
// SimpleRNN fused kernel R16 = R11 with the hh k-loop explicitly software-
// pipelined: A and B fragments for kt+1 are LDSM'd before kt's MMAs (double
// buffers), so shared-memory latency hides under the MMA stream. Bhh register
// cache shrunk 4->2 kts to free the registers for the prefetch buffers.
//   h_{t+1} = tanh(x_t@W_ih^T + b + h_t@W_hh^T), t=0..27; out = h@W_fc^T + b_fc
// Grid: 256 CTAs x 128 threads; CTA = 64 batch rows; warps 2m x 2n (m32n64).
// ============================================================================

#define SM_WHH 0          // 128 x 128 fp16, row stride 256B, swz ^(row&7)
#define SM_WIH 32768      // 128 x 32 fp16, row stride 64B, swz ^(row&3); col28=bias
#define SM_H0  40960      // 64 x 128 fp16 ping
#define SM_H1  57344      // pong
#define SM_WFC 73728      // 10 x 128 fp32
#define SM_BFC 78848      // 10 fp32
#define SM_TOTAL 78912
// post-loop alias: fp32 h28 at smem offset 0, stride 132 floats (33792B)

static __device__ __forceinline__ uint32_t s2u(const void* p) {
    uint32_t a;
    asm("{ .reg .u64 t; cvta.to.shared.u64 t, %1; cvt.u32.u64 %0, t; }"
        : "=r"(a) : "l"(p));
    return a;
}

static __device__ __forceinline__ uint32_t packh(float v0, float v1) {
    uint32_t r;
    asm("cvt.rn.f16x2.f32 %0, %1, %2;" : "=r"(r) : "f"(v1), "f"(v0));
    return r;
}

static __device__ __forceinline__ uint32_t ldpair(const float* p) {
    float2 v = *(const float2*)p;
    return packh(v.x, v.y);
}

static __device__ __forceinline__ float tanh_fast(float v) {
    float r;
    asm("tanh.approx.f32 %0, %1;" : "=f"(r) : "f"(v));
    return r;
}

static __device__ __forceinline__ float tanh_acc(float v) {
    float a = fminf(fmaxf(v * 2.885390082f, -30.0f), 30.0f);
    float e; asm("ex2.approx.f32 %0, %1;" : "=f"(e) : "f"(a));
    float r; asm("rcp.approx.f32 %0, %1;" : "=f"(r) : "f"(e + 1.0f));
    return fmaf(-2.0f, r, 1.0f);
}

#define LDSM4(R, A)                                                              \
    asm volatile("ldmatrix.sync.aligned.m8n8.x4.shared.b16 {%0,%1,%2,%3}, [%4];" \
                 : "=r"((R)[0]), "=r"((R)[1]), "=r"((R)[2]), "=r"((R)[3])        \
                 : "r"(A))

static __device__ __forceinline__ void mma_f16(float* d, const uint32_t* a,
                                               uint32_t b0, uint32_t b1) {
    asm volatile(
        "mma.sync.aligned.m16n8k16.row.col.f32.f16.f16.f32 "
        "{%0,%1,%2,%3}, {%4,%5,%6,%7}, {%8,%9}, {%0,%1,%2,%3};"
        : "+f"(d[0]), "+f"(d[1]), "+f"(d[2]), "+f"(d[3])
        : "r"(a[0]), "r"(a[1]), "r"(a[2]), "r"(a[3]), "r"(b0), "r"(b1));
}

__global__ void __launch_bounds__(128, 2) SimpleRNN_fused_kernel(
    const float* __restrict__ x,    // [16384,1,28,28]
    const float* __restrict__ Wih,  // [128,28]
    const float* __restrict__ Whh,  // [128,128]
    const float* __restrict__ bih,  // [128]
    const float* __restrict__ bhh,  // [128]
    const float* __restrict__ Wfc,  // [10,128]
    const float* __restrict__ bfc,  // [10]
    float* __restrict__ out)        // [16384,10]
{
    extern __shared__ char smem[];
    const uint32_t sb = s2u(smem);
    const int tid  = threadIdx.x;        // 0..127
    const int lane = tid & 31;
    const int wid  = tid >> 5;           // 0..3
    const int m0 = (wid & 1) * 32;       // warp M offset
    const int n0 = (wid >> 1) * 64;      // warp N offset
    const int g = lane >> 2;             // C row in 8-group
    const int q = lane & 3;              // C col pair

    const int rowA = lane & 15;
    const int csA  = lane >> 4;
    const int rowB = ((lane >> 4) << 3) | (lane & 7);
    const int csB  = (lane >> 3) & 1;
    const int l7 = lane & 7, l3 = lane & 3;

    // ---- one-time: weights -> fp16 swizzled SMEM ----
    for (int i = tid; i < 128 * 128; i += 128) {
        int n = i >> 7, k = i & 127;
        uint32_t byte = (uint32_t)(n * 256 + (((k >> 3) ^ (n & 7)) << 4) + (k & 7) * 2);
        *(uint16_t*)(smem + SM_WHH + byte) = __half_as_ushort(__float2half_rn(Whh[i]));
    }
    for (int i = tid; i < 128 * 32; i += 128) {
        int n = i >> 5, k = i & 31;
        float v = (k < 28) ? Wih[n * 28 + k] : ((k == 28) ? (bih[n] + bhh[n]) : 0.0f);
        uint32_t byte = (uint32_t)(n * 64 + (((k >> 3) ^ (n & 3)) << 4) + (k & 7) * 2);
        *(uint16_t*)(smem + SM_WIH + byte) = __half_as_ushort(__float2half_rn(v));
    }
    for (int i = tid; i < 1280; i += 128) ((float*)(smem + SM_WFC))[i] = Wfc[i];
    if (tid < 10) ((float*)(smem + SM_BFC))[tid] = bfc[tid];
    __syncthreads();

    // ---- register caches: Bih all (kt 0,1), Bhh kt 0..1 only ----
    uint32_t Bih[2][4][4];   // [kt][nt2][frag]
    #pragma unroll
    for (int kt = 0; kt < 2; kt++)
        #pragma unroll
        for (int nt2 = 0; nt2 < 4; nt2++)
            LDSM4(Bih[kt][nt2], sb + SM_WIH +
                  (uint32_t)((n0 + nt2 * 16 + rowB) * 64 + (((kt * 2 + csB) ^ l3) << 4)));
    uint32_t Bhh[2][4][4];   // [kt 0..1][nt2][frag]
    #pragma unroll
    for (int kt = 0; kt < 2; kt++)
        #pragma unroll
        for (int nt2 = 0; nt2 < 4; nt2++)
            LDSM4(Bhh[kt][nt2], sb + SM_WHH +
                  (uint32_t)((n0 + nt2 * 16 + rowB) * 256 + (((kt * 2 + csB) ^ l7) << 4)));

    // SMEM addr helpers for the pipelined hh loop
    #define A_ADDR(kt, mt) (sb + Hrd + (uint32_t)((m0 + (mt) * 16 + rowA) * 256 + ((((kt) * 2 + csA) ^ l7) << 4)))
    #define B_ADDR(kt, nt2) (sb + SM_WHH + (uint32_t)((n0 + (nt2) * 16 + rowB) * 256 + ((((kt) * 2 + csB) ^ l7) << 4)))

    // ---- x direct-from-global A-fragment row pointers ----
    const float* pr[2][2];  // [mt][lo/hi]
    #pragma unroll
    for (int mt = 0; mt < 2; mt++) {
        pr[mt][0] = x + ((size_t)blockIdx.x * 64 + m0 + mt * 16 + g) * 784;
        pr[mt][1] = pr[mt][0] + 8 * 784;
    }

    #define LOAD_AX(Ax, tt)                                                        \
        do {                                                                       \
            _Pragma("unroll")                                                      \
            for (int mt = 0; mt < 2; mt++) {                                       \
                const float* rl = pr[mt][0] + (tt) * 28;                           \
                const float* rh = pr[mt][1] + (tt) * 28;                           \
                _Pragma("unroll")                                                  \
                for (int kt = 0; kt < 2; kt++) {                                   \
                    int c0 = kt * 16 + 2 * q;                                      \
                    (Ax)[mt][kt][0] = ldpair(rl + c0);                             \
                    (Ax)[mt][kt][1] = ldpair(rh + c0);                             \
                    if (kt == 0 || q < 2) {                                        \
                        (Ax)[mt][kt][2] = ldpair(rl + c0 + 8);                     \
                        (Ax)[mt][kt][3] = ldpair(rh + c0 + 8);                     \
                    } else if (q == 2) {   /* cols 28,29 = (1.0, 0) bias */        \
                        (Ax)[mt][kt][2] = 0x00003C00u;                             \
                        (Ax)[mt][kt][3] = 0x00003C00u;                             \
                    } else {                                                       \
                        (Ax)[mt][kt][2] = 0u;                                      \
                        (Ax)[mt][kt][3] = 0u;                                      \
                    }                                                              \
                }                                                                  \
            }                                                                      \
        } while (0)

    float acc[2][8][4];      // [mt][n8 0..7][4]
    uint32_t Ax[2][2][4];    // [mt][kt]

    LOAD_AX(Ax, 0);

    #pragma unroll 1
    for (int t = 0; t < 28; t++) {
        const uint32_t Hrd = (t & 1) ? SM_H1 : SM_H0;
        const uint32_t Hwr = (t & 1) ? SM_H0 : SM_H1;

        #pragma unroll
        for (int mt = 0; mt < 2; mt++)
            #pragma unroll
            for (int nt = 0; nt < 8; nt++)
                #pragma unroll
                for (int j = 0; j < 4; j++) acc[mt][nt][j] = 0.0f;

        // ---- x GEMM (K=32): A and B fully register-resident ----
        #pragma unroll
        for (int kt = 0; kt < 2; kt++)
            #pragma unroll
            for (int mt = 0; mt < 2; mt++)
                #pragma unroll
                for (int nt2 = 0; nt2 < 4; nt2++) {
                    mma_f16(acc[mt][2*nt2],   Ax[mt][kt], Bih[kt][nt2][0], Bih[kt][nt2][1]);
                    mma_f16(acc[mt][2*nt2+1], Ax[mt][kt], Bih[kt][nt2][2], Bih[kt][nt2][3]);
                }

        // ---- hh GEMM (K=128), software-pipelined: prefetch kt+1 under kt ----
        if (t > 0) {
            uint32_t Acur[2][4], Anxt[2][4];
            uint32_t Btcur[4][4], Btnxt[4][4];
            // prologue: A(0)
            #pragma unroll
            for (int mt = 0; mt < 2; mt++) LDSM4(Acur[mt], A_ADDR(0, mt));
            #pragma unroll
            for (int kt = 0; kt < 8; kt++) {
                // prefetch next A
                if (kt < 7) {
                    #pragma unroll
                    for (int mt = 0; mt < 2; mt++) LDSM4(Anxt[mt], A_ADDR(kt + 1, mt));
                }
                // prefetch next uncached B (first needed at kt=2)
                if (kt >= 1 && kt < 7) {
                    #pragma unroll
                    for (int nt2 = 0; nt2 < 4; nt2++) LDSM4(Btnxt[nt2], B_ADDR(kt + 1, nt2));
                }
                // MMAs for kt (B: cached for kt<2, else the prefetched buffer)
                if (kt < 2) {
                    #pragma unroll
                    for (int mt = 0; mt < 2; mt++)
                        #pragma unroll
                        for (int nt2 = 0; nt2 < 4; nt2++) {
                            mma_f16(acc[mt][2*nt2],   Acur[mt], Bhh[kt][nt2][0], Bhh[kt][nt2][1]);
                            mma_f16(acc[mt][2*nt2+1], Acur[mt], Bhh[kt][nt2][2], Bhh[kt][nt2][3]);
                        }
                } else {
                    #pragma unroll
                    for (int mt = 0; mt < 2; mt++)
                        #pragma unroll
                        for (int nt2 = 0; nt2 < 4; nt2++) {
                            mma_f16(acc[mt][2*nt2],   Acur[mt], Btcur[nt2][0], Btcur[nt2][1]);
                            mma_f16(acc[mt][2*nt2+1], Acur[mt], Btcur[nt2][2], Btcur[nt2][3]);
                        }
                }
                // rotate buffers
                #pragma unroll
                for (int mt = 0; mt < 2; mt++)
                    #pragma unroll
                    for (int j = 0; j < 4; j++) Acur[mt][j] = Anxt[mt][j];
                #pragma unroll
                for (int nt2 = 0; nt2 < 4; nt2++)
                    #pragma unroll
                    for (int j = 0; j < 4; j++) Btcur[nt2][j] = Btnxt[nt2][j];
            }
        }

        // prefetch x(t+1) A-fragments (LDG in flight under epilogue)
        if (t < 27) LOAD_AX(Ax, t + 1);

        if (t < 27) {
            // h(t+1) = tanh.approx(acc) -> fp16 into Hwr ping-pong
            #pragma unroll
            for (int mt = 0; mt < 2; mt++)
                #pragma unroll
                for (int nt = 0; nt < 8; nt++) {
                    const float* c = acc[mt][nt];
                    int r0 = m0 + mt * 16 + g;
                    int r1 = r0 + 8;
                    int chunk = (n0 >> 3) + nt;
                    uint32_t b0 = (uint32_t)(r0 * 256 + ((chunk ^ (r0 & 7)) << 4) + q * 4);
                    uint32_t b1 = (uint32_t)(r1 * 256 + ((chunk ^ (r1 & 7)) << 4) + q * 4);
                    *(uint32_t*)(smem + Hwr + b0) = packh(tanh_fast(c[0]), tanh_fast(c[1]));
                    *(uint32_t*)(smem + Hwr + b1) = packh(tanh_fast(c[2]), tanh_fast(c[3]));
                }
        } else {
            // final step: accurate tanh, fp32 h28 over dead W_hh; barrier first
            __syncthreads();
            float* h32 = (float*)smem;
            #pragma unroll
            for (int mt = 0; mt < 2; mt++)
                #pragma unroll
                for (int nt = 0; nt < 8; nt++) {
                    const float* c = acc[mt][nt];
                    int r0 = m0 + mt * 16 + g;
                    int col = n0 + nt * 8 + 2 * q;
                    *(float2*)(h32 + r0 * 132 + col)       = make_float2(tanh_acc(c[0]), tanh_acc(c[1]));
                    *(float2*)(h32 + (r0 + 8) * 132 + col) = make_float2(tanh_acc(c[2]), tanh_acc(c[3]));
                }
        }
        __syncthreads();
    }

    // ---- fc: out = h28 @ W_fc^T + b_fc (fp32 SIMT, 128 threads) ----
    {
        const float* h32  = (const float*)smem;
        const float* wfc  = (const float*)(smem + SM_WFC);
        const float* bfcS = (const float*)(smem + SM_BFC);
        int r = tid >> 1;
        int c0 = (tid & 1) * 5;
        float s[5];
        #pragma unroll
        for (int j = 0; j < 5; j++) s[j] = bfcS[c0 + j];
        const float4* hr = (const float4*)(h32 + r * 132);
        #pragma unroll 8
        for (int k4 = 0; k4 < 32; k4++) {
            float4 hv = hr[k4];
            #pragma unroll
            for (int j = 0; j < 5; j++) {
                float4 wv = ((const float4*)(wfc + (c0 + j) * 128))[k4];
                s[j] += hv.x * wv.x + hv.y * wv.y + hv.z * wv.z + hv.w * wv.w;
            }
        }
        float* o = out + ((size_t)blockIdx.x * 64 + r) * 10 + c0;
        #pragma unroll
        for (int j = 0; j < 5; j++) o[j] = s[j];
    }
}

extern "C" void kernel_launch(void* const* d_in, const int* in_sizes, int n_in,
                              void* d_out, int out_size) {
    const float* x   = (const float*)d_in[0];
    const float* Wih = (const float*)d_in[1];
    const float* Whh = (const float*)d_in[2];
    const float* bih = (const float*)d_in[3];
    const float* bhh = (const float*)d_in[4];
    const float* Wfc = (const float*)d_in[5];
    const float* bfc = (const float*)d_in[6];
    float* out = (float*)d_out;

    cudaFuncSetAttribute(SimpleRNN_fused_kernel,
                         cudaFuncAttributeMaxDynamicSharedMemorySize, SM_TOTAL);
    SimpleRNN_fused_kernel<<<256, 128, SM_TOTAL>>>(x, Wih, Whh, bih, bhh, Wfc, bfc, out);
}

// round 17
// speedup vs baseline: 1.1230x; 1.1230x over previous
#include <cuda_runtime.h>
#include <cuda_fp16.h>
#include <cstdint>

// ============================================================================
// SimpleRNN fused kernel R17 = R11 steady-state loop verbatim (the measured
// optimum: m32n64 warps, 2 CTAs/SM, Bih fully + Bhh half register-cached,
// h ping-pong in SMEM, x A-fragments direct from global) + vectorized Whh
// prologue (LDG.128/STS.64 instead of scalar).
//   h_{t+1} = tanh(x_t@W_ih^T + b + h_t@W_hh^T), t=0..27; out = h@W_fc^T + b_fc
// Grid: 256 CTAs x 128 threads; CTA = 64 batch rows; warps 2m x 2n (m32n64).
// ============================================================================

#define SM_WHH 0          // 128 x 128 fp16, row stride 256B, swz ^(row&7)
#define SM_WIH 32768      // 128 x 32 fp16, row stride 64B, swz ^(row&3); col28=bias
#define SM_H0  40960      // 64 x 128 fp16 ping
#define SM_H1  57344      // pong
#define SM_WFC 73728      // 10 x 128 fp32
#define SM_BFC 78848      // 10 fp32
#define SM_TOTAL 78912
// post-loop alias: fp32 h28 at smem offset 0, stride 132 floats (33792B)

static __device__ __forceinline__ uint32_t s2u(const void* p) {
    uint32_t a;
    asm("{ .reg .u64 t; cvta.to.shared.u64 t, %1; cvt.u32.u64 %0, t; }"
        : "=r"(a) : "l"(p));
    return a;
}

static __device__ __forceinline__ uint32_t packh(float v0, float v1) {
    uint32_t r;
    asm("cvt.rn.f16x2.f32 %0, %1, %2;" : "=r"(r) : "f"(v1), "f"(v0));
    return r;
}

static __device__ __forceinline__ uint32_t ldpair(const float* p) {
    float2 v = *(const float2*)p;
    return packh(v.x, v.y);
}

static __device__ __forceinline__ float tanh_fast(float v) {
    float r;
    asm("tanh.approx.f32 %0, %1;" : "=f"(r) : "f"(v));
    return r;
}

static __device__ __forceinline__ float tanh_acc(float v) {
    float a = fminf(fmaxf(v * 2.885390082f, -30.0f), 30.0f);
    float e; asm("ex2.approx.f32 %0, %1;" : "=f"(e) : "f"(a));
    float r; asm("rcp.approx.f32 %0, %1;" : "=f"(r) : "f"(e + 1.0f));
    return fmaf(-2.0f, r, 1.0f);
}

#define LDSM4(R, A)                                                              \
    asm volatile("ldmatrix.sync.aligned.m8n8.x4.shared.b16 {%0,%1,%2,%3}, [%4];" \
                 : "=r"((R)[0]), "=r"((R)[1]), "=r"((R)[2]), "=r"((R)[3])        \
                 : "r"(A))

static __device__ __forceinline__ void mma_f16(float* d, const uint32_t* a,
                                               uint32_t b0, uint32_t b1) {
    asm volatile(
        "mma.sync.aligned.m16n8k16.row.col.f32.f16.f16.f32 "
        "{%0,%1,%2,%3}, {%4,%5,%6,%7}, {%8,%9}, {%0,%1,%2,%3};"
        : "+f"(d[0]), "+f"(d[1]), "+f"(d[2]), "+f"(d[3])
        : "r"(a[0]), "r"(a[1]), "r"(a[2]), "r"(a[3]), "r"(b0), "r"(b1));
}

__global__ void __launch_bounds__(128, 2) SimpleRNN_fused_kernel(
    const float* __restrict__ x,    // [16384,1,28,28]
    const float* __restrict__ Wih,  // [128,28]
    const float* __restrict__ Whh,  // [128,128]
    const float* __restrict__ bih,  // [128]
    const float* __restrict__ bhh,  // [128]
    const float* __restrict__ Wfc,  // [10,128]
    const float* __restrict__ bfc,  // [10]
    float* __restrict__ out)        // [16384,10]
{
    extern __shared__ char smem[];
    const uint32_t sb = s2u(smem);
    const int tid  = threadIdx.x;        // 0..127
    const int lane = tid & 31;
    const int wid  = tid >> 5;           // 0..3
    const int m0 = (wid & 1) * 32;       // warp M offset
    const int n0 = (wid >> 1) * 64;      // warp N offset
    const int g = lane >> 2;             // C row in 8-group
    const int q = lane & 3;              // C col pair

    const int rowA = lane & 15;
    const int csA  = lane >> 4;
    const int rowB = ((lane >> 4) << 3) | (lane & 7);
    const int csB  = (lane >> 3) & 1;
    const int l7 = lane & 7, l3 = lane & 3;

    // ---- one-time: weights -> fp16 swizzled SMEM (Whh vectorized) ----
    // k aligned to 4: the 4 halves land contiguously inside one 16B swizzle
    // group -> single st.shared.b64.
    for (int i = tid * 4; i < 128 * 128; i += 128 * 4) {
        int n = i >> 7, k = i & 127;
        float4 v = *(const float4*)(Whh + i);
        uint32_t p0 = packh(v.x, v.y);
        uint32_t p1 = packh(v.z, v.w);
        uint32_t byte = (uint32_t)(n * 256 + (((k >> 3) ^ (n & 7)) << 4) + (k & 7) * 2);
        asm volatile("st.shared.v2.b32 [%0], {%1, %2};"
                     :: "r"(sb + SM_WHH + byte), "r"(p0), "r"(p1) : "memory");
    }
    for (int i = tid; i < 128 * 32; i += 128) {
        int n = i >> 5, k = i & 31;
        float v = (k < 28) ? Wih[n * 28 + k] : ((k == 28) ? (bih[n] + bhh[n]) : 0.0f);
        uint32_t byte = (uint32_t)(n * 64 + (((k >> 3) ^ (n & 3)) << 4) + (k & 7) * 2);
        *(uint16_t*)(smem + SM_WIH + byte) = __half_as_ushort(__float2half_rn(v));
    }
    for (int i = tid; i < 1280; i += 128) ((float*)(smem + SM_WFC))[i] = Wfc[i];
    if (tid < 10) ((float*)(smem + SM_BFC))[tid] = bfc[tid];
    __syncthreads();

    // ---- register caches: Bih all (kt 0,1), Bhh first half (kt 0..3) ----
    uint32_t Bih[2][4][4];   // [kt][nt2][frag]
    #pragma unroll
    for (int kt = 0; kt < 2; kt++)
        #pragma unroll
        for (int nt2 = 0; nt2 < 4; nt2++)
            LDSM4(Bih[kt][nt2], sb + SM_WIH +
                  (uint32_t)((n0 + nt2 * 16 + rowB) * 64 + (((kt * 2 + csB) ^ l3) << 4)));
    uint32_t Bhh[4][4][4];   // [kt 0..3][nt2][frag]
    #pragma unroll
    for (int kt = 0; kt < 4; kt++)
        #pragma unroll
        for (int nt2 = 0; nt2 < 4; nt2++)
            LDSM4(Bhh[kt][nt2], sb + SM_WHH +
                  (uint32_t)((n0 + nt2 * 16 + rowB) * 256 + (((kt * 2 + csB) ^ l7) << 4)));

    // ---- x direct-from-global A-fragment row pointers ----
    const float* pr[2][2];  // [mt][lo/hi]
    #pragma unroll
    for (int mt = 0; mt < 2; mt++) {
        pr[mt][0] = x + ((size_t)blockIdx.x * 64 + m0 + mt * 16 + g) * 784;
        pr[mt][1] = pr[mt][0] + 8 * 784;
    }

    #define LOAD_AX(Ax, tt)                                                        \
        do {                                                                       \
            _Pragma("unroll")                                                      \
            for (int mt = 0; mt < 2; mt++) {                                       \
                const float* rl = pr[mt][0] + (tt) * 28;                           \
                const float* rh = pr[mt][1] + (tt) * 28;                           \
                _Pragma("unroll")                                                  \
                for (int kt = 0; kt < 2; kt++) {                                   \
                    int c0 = kt * 16 + 2 * q;                                      \
                    (Ax)[mt][kt][0] = ldpair(rl + c0);                             \
                    (Ax)[mt][kt][1] = ldpair(rh + c0);                             \
                    if (kt == 0 || q < 2) {                                        \
                        (Ax)[mt][kt][2] = ldpair(rl + c0 + 8);                     \
                        (Ax)[mt][kt][3] = ldpair(rh + c0 + 8);                     \
                    } else if (q == 2) {   /* cols 28,29 = (1.0, 0) bias */        \
                        (Ax)[mt][kt][2] = 0x00003C00u;                             \
                        (Ax)[mt][kt][3] = 0x00003C00u;                             \
                    } else {                                                       \
                        (Ax)[mt][kt][2] = 0u;                                      \
                        (Ax)[mt][kt][3] = 0u;                                      \
                    }                                                              \
                }                                                                  \
            }                                                                      \
        } while (0)

    float acc[2][8][4];      // [mt][n8 0..7][4]
    uint32_t Ax[2][2][4];    // [mt][kt]

    LOAD_AX(Ax, 0);

    #pragma unroll 1
    for (int t = 0; t < 28; t++) {
        const uint32_t Hrd = (t & 1) ? SM_H1 : SM_H0;
        const uint32_t Hwr = (t & 1) ? SM_H0 : SM_H1;

        #pragma unroll
        for (int mt = 0; mt < 2; mt++)
            #pragma unroll
            for (int nt = 0; nt < 8; nt++)
                #pragma unroll
                for (int j = 0; j < 4; j++) acc[mt][nt][j] = 0.0f;

        // ---- x GEMM (K=32): A and B fully register-resident ----
        #pragma unroll
        for (int kt = 0; kt < 2; kt++)
            #pragma unroll
            for (int mt = 0; mt < 2; mt++)
                #pragma unroll
                for (int nt2 = 0; nt2 < 4; nt2++) {
                    mma_f16(acc[mt][2*nt2],   Ax[mt][kt], Bih[kt][nt2][0], Bih[kt][nt2][1]);
                    mma_f16(acc[mt][2*nt2+1], Ax[mt][kt], Bih[kt][nt2][2], Bih[kt][nt2][3]);
                }

        // ---- hh GEMM (K=128): A via LDSM; B kt<4 cached, kt>=4 LDSM ----
        if (t > 0) {
            #pragma unroll
            for (int kt = 0; kt < 8; kt++) {
                uint32_t A[2][4];
                #pragma unroll
                for (int mt = 0; mt < 2; mt++)
                    LDSM4(A[mt], sb + Hrd +
                          (uint32_t)((m0 + mt * 16 + rowA) * 256 + (((kt * 2 + csA) ^ l7) << 4)));
                if (kt < 4) {
                    #pragma unroll
                    for (int mt = 0; mt < 2; mt++)
                        #pragma unroll
                        for (int nt2 = 0; nt2 < 4; nt2++) {
                            mma_f16(acc[mt][2*nt2],   A[mt], Bhh[kt][nt2][0], Bhh[kt][nt2][1]);
                            mma_f16(acc[mt][2*nt2+1], A[mt], Bhh[kt][nt2][2], Bhh[kt][nt2][3]);
                        }
                } else {
                    uint32_t Bt[4][4];
                    #pragma unroll
                    for (int nt2 = 0; nt2 < 4; nt2++)
                        LDSM4(Bt[nt2], sb + SM_WHH +
                              (uint32_t)((n0 + nt2 * 16 + rowB) * 256 + (((kt * 2 + csB) ^ l7) << 4)));
                    #pragma unroll
                    for (int mt = 0; mt < 2; mt++)
                        #pragma unroll
                        for (int nt2 = 0; nt2 < 4; nt2++) {
                            mma_f16(acc[mt][2*nt2],   A[mt], Bt[nt2][0], Bt[nt2][1]);
                            mma_f16(acc[mt][2*nt2+1], A[mt], Bt[nt2][2], Bt[nt2][3]);
                        }
                }
            }
        }

        // prefetch x(t+1) A-fragments (LDG in flight under epilogue)
        if (t < 27) LOAD_AX(Ax, t + 1);

        if (t < 27) {
            // h(t+1) = tanh.approx(acc) -> fp16 into Hwr ping-pong
            #pragma unroll
            for (int mt = 0; mt < 2; mt++)
                #pragma unroll
                for (int nt = 0; nt < 8; nt++) {
                    const float* c = acc[mt][nt];
                    int r0 = m0 + mt * 16 + g;
                    int r1 = r0 + 8;
                    int chunk = (n0 >> 3) + nt;
                    uint32_t b0 = (uint32_t)(r0 * 256 + ((chunk ^ (r0 & 7)) << 4) + q * 4);
                    uint32_t b1 = (uint32_t)(r1 * 256 + ((chunk ^ (r1 & 7)) << 4) + q * 4);
                    *(uint32_t*)(smem + Hwr + b0) = packh(tanh_fast(c[0]), tanh_fast(c[1]));
                    *(uint32_t*)(smem + Hwr + b1) = packh(tanh_fast(c[2]), tanh_fast(c[3]));
                }
        } else {
            // final step: accurate tanh, fp32 h28 over dead W_hh; barrier first
            __syncthreads();
            float* h32 = (float*)smem;
            #pragma unroll
            for (int mt = 0; mt < 2; mt++)
                #pragma unroll
                for (int nt = 0; nt < 8; nt++) {
                    const float* c = acc[mt][nt];
                    int r0 = m0 + mt * 16 + g;
                    int col = n0 + nt * 8 + 2 * q;
                    *(float2*)(h32 + r0 * 132 + col)       = make_float2(tanh_acc(c[0]), tanh_acc(c[1]));
                    *(float2*)(h32 + (r0 + 8) * 132 + col) = make_float2(tanh_acc(c[2]), tanh_acc(c[3]));
                }
        }
        __syncthreads();
    }

    // ---- fc: out = h28 @ W_fc^T + b_fc (fp32 SIMT, 128 threads) ----
    {
        const float* h32  = (const float*)smem;
        const float* wfc  = (const float*)(smem + SM_WFC);
        const float* bfcS = (const float*)(smem + SM_BFC);
        int r = tid >> 1;
        int c0 = (tid & 1) * 5;
        float s[5];
        #pragma unroll
        for (int j = 0; j < 5; j++) s[j] = bfcS[c0 + j];
        const float4* hr = (const float4*)(h32 + r * 132);
        #pragma unroll 8
        for (int k4 = 0; k4 < 32; k4++) {
            float4 hv = hr[k4];
            #pragma unroll
            for (int j = 0; j < 5; j++) {
                float4 wv = ((const float4*)(wfc + (c0 + j) * 128))[k4];
                s[j] += hv.x * wv.x + hv.y * wv.y + hv.z * wv.z + hv.w * wv.w;
            }
        }
        float* o = out + ((size_t)blockIdx.x * 64 + r) * 10 + c0;
        #pragma unroll
        for (int j = 0; j < 5; j++) o[j] = s[j];
    }
}

extern "C" void kernel_launch(void* const* d_in, const int* in_sizes, int n_in,
                              void* d_out, int out_size) {
    const float* x   = (const float*)d_in[0];
    const float* Wih = (const float*)d_in[1];
    const float* Whh = (const float*)d_in[2];
    const float* bih = (const float*)d_in[3];
    const float* bhh = (const float*)d_in[4];
    const float* Wfc = (const float*)d_in[5];
    const float* bfc = (const float*)d_in[6];
    float* out = (float*)d_out;

    cudaFuncSetAttribute(SimpleRNN_fused_kernel,
                         cudaFuncAttributeMaxDynamicSharedMemorySize, SM_TOTAL);
    SimpleRNN_fused_kernel<<<256, 128, SM_TOTAL>>>(x, Wih, Whh, bih, bhh, Wfc, bfc, out);
}